// round 8
// baseline (speedup 1.0000x reference)
#include <cuda_runtime.h>

#define ALPHA 0.95f
#define NUM_CLASSES 32000
#define VEC4 (NUM_CLASSES / 4)      // 8000 float4 per row
#define THREADS 1024
#define PER_T 8                     // covers 8000 with predication
#define GRID_CTAS 160               // >= SM count (152 on GB300); extras drain harmlessly

__device__ int g_row_ctr;

__global__ void kd_reset_ctr()
{
    g_row_ctr = 0;
}

__global__ __launch_bounds__(THREADS, 1)
void kd_scale_kernel(const float* __restrict__ logits,
                     const int* __restrict__ labels,   // int32 (JAX x64 disabled)
                     float* __restrict__ out,
                     int batch)
{
    const int tid = threadIdx.x;
    const int wid = tid >> 5;
    const int lid = tid & 31;

    __shared__ float warpsum[THREADS / 32];
    __shared__ float bcast[2];
    __shared__ int   row_s;

    if (tid == 0) row_s = atomicAdd(&g_row_ctr, 1);
    __syncthreads();
    int row = row_s;

    float4 pf0, pf1;
    bool have_pf = false;

    while (row < batch) {
        const float4* __restrict__ in4  = (const float4*)(logits + (size_t)row * NUM_CLASSES);
        float4* __restrict__       out4 = (float4*)(out    + (size_t)row * NUM_CLASSES);
        const int label = __ldg(labels + row);

        // ---- Phase 1: load row into registers (use carried prefetch), partial sum ----
        float4 v[PER_T];
        if (have_pf) {
            v[0] = pf0;
            v[1] = pf1;
        } else {
            v[0] = __ldcs(in4 + tid);
            v[1] = __ldcs(in4 + tid + THREADS);
        }
        float partial = (v[0].x + v[0].y) + (v[0].z + v[0].w)
                      + (v[1].x + v[1].y) + (v[1].z + v[1].w);
#pragma unroll
        for (int k = 2; k < PER_T; k++) {
            const int idx = tid + k * THREADS;
            if (idx < VEC4) {
                v[k] = __ldcs(in4 + idx);
                partial += (v[k].x + v[k].y) + (v[k].z + v[k].w);
            }
        }

        // Grab next ticket early (made visible to the block by the barrier below)
        if (tid == 0) row_s = atomicAdd(&g_row_ctr, 1);

        // ---- Block reduction, stage 1 ----
#pragma unroll
        for (int o = 16; o; o >>= 1)
            partial += __shfl_xor_sync(0xFFFFFFFFu, partial, o);
        if (lid == 0) warpsum[wid] = partial;
        __syncthreads();

        const int nextrow = row_s;

        // ---- Prefetch next row's first 2 vectors while warp 0 finishes the reduce ----
        have_pf = (nextrow < batch);
        if (have_pf) {
            const float4* __restrict__ nin4 =
                (const float4*)(logits + (size_t)nextrow * NUM_CLASSES);
            pf0 = __ldcs(nin4 + tid);
            pf1 = __ldcs(nin4 + tid + THREADS);
        }

        if (wid == 0) {
            float s = (lid < THREADS / 32) ? warpsum[lid] : 0.0f;
#pragma unroll
            for (int o = 16; o; o >>= 1)
                s += __shfl_xor_sync(0xFFFFFFFFu, s, o);
            if (lid == 0) {
                const float S  = s;
                const float t  = __ldg(logits + (size_t)row * NUM_CLASSES + label);
                const float sc = ALPHA / (1.0f + S - 2.0f * t);
                bcast[0] = sc;
                bcast[1] = 1.0f - sc * S;   // corr
            }
        }
        __syncthreads();

        const float sc    = bcast[0];
        const float corr  = bcast[1];
        const int   lvec  = label >> 2;
        const int   lcomp = label & 3;

        // ---- Phase 2: scale from registers, streaming stores ----
#pragma unroll
        for (int k = 0; k < PER_T; k++) {
            const int idx = tid + k * THREADS;
            if (idx < VEC4) {
                float4 r;
                r.x = sc * v[k].x;
                r.y = sc * v[k].y;
                r.z = sc * v[k].z;
                r.w = sc * v[k].w;
                if (idx == lvec) {
                    ((float*)&r)[lcomp] += corr;
                }
                __stcs(out4 + idx, r);
            }
        }

        row = nextrow;
    }
}

extern "C" void kernel_launch(void* const* d_in, const int* in_sizes, int n_in,
                              void* d_out, int out_size)
{
    const float* logits = (const float*)d_in[0];
    const int*   labels = (const int*)d_in[1];
    float*       out    = (float*)d_out;

    const int batch = in_sizes[1];   // labels element count == BATCH

    kd_reset_ctr<<<1, 1>>>();
    kd_scale_kernel<<<GRID_CTAS, THREADS>>>(logits, labels, out, batch);
}

// round 9
// speedup vs baseline: 1.1068x; 1.1068x over previous
#include <cuda_runtime.h>

#define ALPHA 0.95f
#define NUM_CLASSES 32000
#define VEC4 (NUM_CLASSES / 4)      // 8000 float4 per row
#define THREADS 512
#define TOT_K 16                    // 512*16 = 8192 >= 8000 (k=15 predicated)
#define NREG 6                      // k=0..5 live in registers
#define NSMEM (TOT_K - NREG)        // k=6..15 staged in shared memory
#define STAGE_BYTES (NSMEM * THREADS * 16)   // 10*512*16 = 81920 B

extern __shared__ float4 stage[];   // [NSMEM * THREADS]

__global__ __launch_bounds__(THREADS, 2)
void kd_scale_kernel(const float* __restrict__ logits,
                     const int* __restrict__ labels,   // int32 (JAX x64 disabled)
                     float* __restrict__ out)
{
    const int row = blockIdx.x;
    const int tid = threadIdx.x;
    const int wid = tid >> 5;
    const int lid = tid & 31;

    const float4* __restrict__ in4  = (const float4*)(logits + (size_t)row * NUM_CLASSES);
    float4* __restrict__       out4 = (float4*)(out    + (size_t)row * NUM_CLASSES);

    const int label = __ldg(labels + row);
    const int lvec  = label >> 2;
    const int lcomp = label & 3;

    // ---- Phase 1: read row once; 6 vec4 -> regs, 10 vec4 -> smem stage ----
    float4 v[NREG];
    float partial = 0.0f;
#pragma unroll
    for (int k = 0; k < NREG; k++) {
        v[k] = __ldcs(in4 + tid + k * THREADS);
        partial += (v[k].x + v[k].y) + (v[k].z + v[k].w);
    }
#pragma unroll
    for (int k = NREG; k < TOT_K; k++) {
        const int idx = tid + k * THREADS;
        if (idx < VEC4) {
            float4 w = __ldcs(in4 + idx);
            partial += (w.x + w.y) + (w.z + w.w);
            stage[(k - NREG) * THREADS + tid] = w;
        }
    }

    // ---- Block reduction ----
#pragma unroll
    for (int o = 16; o; o >>= 1)
        partial += __shfl_xor_sync(0xFFFFFFFFu, partial, o);

    __shared__ float warpsum[THREADS / 32];
    __shared__ float bcast[2];
    if (lid == 0) warpsum[wid] = partial;
    __syncthreads();

    if (wid == 0) {
        float s = (lid < THREADS / 32) ? warpsum[lid] : 0.0f;
#pragma unroll
        for (int o = 16; o; o >>= 1)
            s += __shfl_xor_sync(0xFFFFFFFFu, s, o);
        if (lid == 0) {
            const float S  = s;
            const float t  = __ldg(logits + (size_t)row * NUM_CLASSES + label);
            const float sc = ALPHA / (1.0f + S - 2.0f * t);
            bcast[0] = sc;
            bcast[1] = 1.0f - sc * S;   // corr
        }
    }
    __syncthreads();

    const float sc   = bcast[0];
    const float corr = bcast[1];

    // ---- Phase 2: scale (regs + smem stage), streaming stores ----
#pragma unroll
    for (int k = 0; k < NREG; k++) {
        const int idx = tid + k * THREADS;
        float4 r;
        r.x = sc * v[k].x;
        r.y = sc * v[k].y;
        r.z = sc * v[k].z;
        r.w = sc * v[k].w;
        if (idx == lvec) ((float*)&r)[lcomp] += corr;
        __stcs(out4 + idx, r);
    }
#pragma unroll
    for (int k = NREG; k < TOT_K; k++) {
        const int idx = tid + k * THREADS;
        if (idx < VEC4) {
            float4 w = stage[(k - NREG) * THREADS + tid];
            float4 r;
            r.x = sc * w.x;
            r.y = sc * w.y;
            r.z = sc * w.z;
            r.w = sc * w.w;
            if (idx == lvec) ((float*)&r)[lcomp] += corr;
            __stcs(out4 + idx, r);
        }
    }
}

extern "C" void kernel_launch(void* const* d_in, const int* in_sizes, int n_in,
                              void* d_out, int out_size)
{
    const float* logits = (const float*)d_in[0];
    const int*   labels = (const int*)d_in[1];
    float*       out    = (float*)d_out;

    const int batch = in_sizes[1];   // labels element count == BATCH

    // Opt in to >48KB dynamic smem (idempotent, deterministic, no allocation).
    cudaFuncSetAttribute(kd_scale_kernel,
                         cudaFuncAttributeMaxDynamicSharedMemorySize,
                         STAGE_BYTES);

    kd_scale_kernel<<<batch, THREADS, STAGE_BYTES>>>(logits, labels, out);
}